// round 2
// baseline (speedup 1.0000x reference)
#include <cuda_runtime.h>
#include <cuda_bf16.h>

#define NN 50000
#define NE 800000
#define DD 64

// Scratch (static device globals — no allocation allowed)
__device__ float g_neigh[NN * DD];
__device__ float g_z2[NN * DD];
__device__ float g_sum[DD];
__device__ float g_sqs[DD];

// ---------------------------------------------------------------------------
// K1: neigh = h  (GIN eps = 0 -> (1+eps)*h is just h), zero stat accumulators
// ---------------------------------------------------------------------------
__global__ void k_init(const float4* __restrict__ h4) {
    int i = blockIdx.x * blockDim.x + threadIdx.x;
    const int tot = NN * DD / 4;
    if (i < tot) ((float4*)g_neigh)[i] = h4[i];
    if (blockIdx.x == 0 && threadIdx.x < DD) {
        g_sum[threadIdx.x] = 0.f;
        g_sqs[threadIdx.x] = 0.f;
    }
}

// ---------------------------------------------------------------------------
// K2: scatter-add  neigh[dst] += h[src]   (16 lanes per edge, float4 each)
//     NOTE: indices are int32 (JAX x64 disabled -> int64 request gives int32)
// ---------------------------------------------------------------------------
__global__ void k_scatter(const float4* __restrict__ h4,
                          const int* __restrict__ src,
                          const int* __restrict__ dst) {
    int t = blockIdx.x * blockDim.x + threadIdx.x;
    int e = t >> 4;
    int part = t & 15;
    if (e >= NE) return;
    int s = src[e];
    int d = dst[e];
    float4 v = __ldg(&h4[(size_t)s * 16 + part]);
    float* p = &g_neigh[(size_t)d * DD + part * 4];
    asm volatile("red.global.add.v4.f32 [%0], {%1,%2,%3,%4};"
                 :: "l"(p), "f"(v.x), "f"(v.y), "f"(v.z), "f"(v.w)
                 : "memory");
}

// ---------------------------------------------------------------------------
// K3: per-node MLP  z2 = relu(z@W1+b1)@W2+b2, fused BN-stat accumulation
//     128 nodes/block, 256 threads: each thread 8 nodes x 4 cols
// ---------------------------------------------------------------------------
__global__ void __launch_bounds__(256) k_mlp(const float* __restrict__ W1,
                                             const float* __restrict__ b1,
                                             const float* __restrict__ W2,
                                             const float* __restrict__ b2) {
    __shared__ float sZ[128 * DD];   // 32 KB: node tile (z, then y1)
    __shared__ float sW[DD * DD];    // 16 KB: transposed weights (then reduce buf)

    const int tid = threadIdx.x;
    const int node0 = blockIdx.x * 128;
    const int nvalid = min(128, NN - node0);

    // load z tile (float4 vectorized), zero-fill invalid tail rows
    for (int i = tid; i < 128 * 16; i += 256) {
        float4 v = (i < nvalid * 16) ? ((const float4*)g_neigh)[node0 * 16 + i]
                                     : make_float4(0.f, 0.f, 0.f, 0.f);
        ((float4*)sZ)[i] = v;
    }
    // load W1 transposed: sW[j*64 + k] = W1[k*64 + j]
    for (int i = tid; i < DD * DD; i += 256) {
        int k = i >> 6, j = i & 63;
        sW[j * DD + k] = W1[i];
    }
    __syncthreads();

    const int jg = tid & 15;        // col group: cols j0..j0+3
    const int ng = tid >> 4;        // node group: nodes n0..n0+7
    const int j0 = jg * 4;
    const int n0 = ng * 8;

    float acc[8][4];
    {
        float bb0 = b1[j0], bb1 = b1[j0 + 1], bb2 = b1[j0 + 2], bb3 = b1[j0 + 3];
        #pragma unroll
        for (int n = 0; n < 8; n++) {
            acc[n][0] = bb0; acc[n][1] = bb1; acc[n][2] = bb2; acc[n][3] = bb3;
        }
    }

    // ---- layer 1 ----
    #pragma unroll
    for (int k0 = 0; k0 < DD; k0 += 4) {
        float4 w[4];
        #pragma unroll
        for (int c = 0; c < 4; c++)
            w[c] = *(const float4*)&sW[(j0 + c) * DD + k0];
        #pragma unroll
        for (int n = 0; n < 8; n++) {
            float4 a = *(const float4*)&sZ[(n0 + n) * DD + k0];
            #pragma unroll
            for (int c = 0; c < 4; c++) {
                acc[n][c] = fmaf(a.x, w[c].x, acc[n][c]);
                acc[n][c] = fmaf(a.y, w[c].y, acc[n][c]);
                acc[n][c] = fmaf(a.z, w[c].z, acc[n][c]);
                acc[n][c] = fmaf(a.w, w[c].w, acc[n][c]);
            }
        }
    }
    __syncthreads();   // all reads of sZ / sW done

    // write y1 = relu(acc) back into sZ; reload sW with W2^T
    #pragma unroll
    for (int n = 0; n < 8; n++)
        #pragma unroll
        for (int c = 0; c < 4; c++)
            sZ[(n0 + n) * DD + j0 + c] = fmaxf(acc[n][c], 0.f);
    for (int i = tid; i < DD * DD; i += 256) {
        int k = i >> 6, j = i & 63;
        sW[j * DD + k] = W2[i];
    }
    __syncthreads();

    // ---- layer 2 ----
    {
        float bb0 = b2[j0], bb1 = b2[j0 + 1], bb2v = b2[j0 + 2], bb3 = b2[j0 + 3];
        #pragma unroll
        for (int n = 0; n < 8; n++) {
            acc[n][0] = bb0; acc[n][1] = bb1; acc[n][2] = bb2v; acc[n][3] = bb3;
        }
    }
    #pragma unroll
    for (int k0 = 0; k0 < DD; k0 += 4) {
        float4 w[4];
        #pragma unroll
        for (int c = 0; c < 4; c++)
            w[c] = *(const float4*)&sW[(j0 + c) * DD + k0];
        #pragma unroll
        for (int n = 0; n < 8; n++) {
            float4 a = *(const float4*)&sZ[(n0 + n) * DD + k0];
            #pragma unroll
            for (int c = 0; c < 4; c++) {
                acc[n][c] = fmaf(a.x, w[c].x, acc[n][c]);
                acc[n][c] = fmaf(a.y, w[c].y, acc[n][c]);
                acc[n][c] = fmaf(a.z, w[c].z, acc[n][c]);
                acc[n][c] = fmaf(a.w, w[c].w, acc[n][c]);
            }
        }
    }

    // store z2 + local BN partial sums
    float s[4] = {0.f, 0.f, 0.f, 0.f};
    float q[4] = {0.f, 0.f, 0.f, 0.f};
    #pragma unroll
    for (int n = 0; n < 8; n++) {
        int node = node0 + n0 + n;
        if (node < NN) {
            ((float4*)g_z2)[node * 16 + jg] =
                make_float4(acc[n][0], acc[n][1], acc[n][2], acc[n][3]);
            #pragma unroll
            for (int c = 0; c < 4; c++) {
                float v = acc[n][c];
                s[c] += v;
                q[c] += v * v;
            }
        }
    }

    __syncthreads();           // done with sW contents; reuse as reduce buffer
    float* sRed = sW;          // 256 threads * 8 floats = 8 KB
    #pragma unroll
    for (int c = 0; c < 4; c++) {
        sRed[tid * 8 + c] = s[c];
        sRed[tid * 8 + 4 + c] = q[c];
    }
    __syncthreads();
    if (tid < DD) {
        int jg2 = tid >> 2, c2 = tid & 3;   // dim = jg2*4 + c2 == tid
        float a = 0.f, b = 0.f;
        #pragma unroll
        for (int g = 0; g < 16; g++) {
            int t2 = jg2 + g * 16;
            a += sRed[t2 * 8 + c2];
            b += sRed[t2 * 8 + 4 + c2];
        }
        atomicAdd(&g_sum[tid], a);
        atomicAdd(&g_sqs[tid], b);
    }
}

// ---------------------------------------------------------------------------
// K4: out = h + relu( z2 * scale + shift )   (scale/shift derived per block)
// ---------------------------------------------------------------------------
__global__ void k_bn(const float4* __restrict__ h4,
                     const float* __restrict__ gamma,
                     const float* __restrict__ beta,
                     float4* __restrict__ out4) {
    __shared__ float sA[DD], sB[DD];
    if (threadIdx.x < DD) {
        const float invN = 1.0f / (float)NN;
        float m = g_sum[threadIdx.x] * invN;
        float v = g_sqs[threadIdx.x] * invN - m * m;
        float a = gamma[threadIdx.x] * rsqrtf(v + 1e-5f);
        sA[threadIdx.x] = a;
        sB[threadIdx.x] = beta[threadIdx.x] - m * a;
    }
    __syncthreads();
    int i = blockIdx.x * blockDim.x + threadIdx.x;   // float4 index
    if (i < NN * 16) {
        float4 z = ((const float4*)g_z2)[i];
        float4 hv = h4[i];
        int dg = (i & 15) * 4;
        float4 o;
        o.x = hv.x + fmaxf(fmaf(z.x, sA[dg + 0], sB[dg + 0]), 0.f);
        o.y = hv.y + fmaxf(fmaf(z.y, sA[dg + 1], sB[dg + 1]), 0.f);
        o.z = hv.z + fmaxf(fmaf(z.z, sA[dg + 2], sB[dg + 2]), 0.f);
        o.w = hv.w + fmaxf(fmaf(z.w, sA[dg + 3], sB[dg + 3]), 0.f);
        out4[i] = o;
    }
}

// ---------------------------------------------------------------------------
extern "C" void kernel_launch(void* const* d_in, const int* in_sizes, int n_in,
                              void* d_out, int out_size) {
    const float* h     = (const float*)d_in[0];
    const float* W1    = (const float*)d_in[1];
    const float* b1    = (const float*)d_in[2];
    const float* W2    = (const float*)d_in[3];
    const float* b2    = (const float*)d_in[4];
    const float* gamma = (const float*)d_in[5];
    const float* beta  = (const float*)d_in[6];
    const int* src     = (const int*)d_in[7];
    const int* dst     = (const int*)d_in[8];

    (void)in_sizes; (void)n_in; (void)out_size;

    const int copy_blocks = (NN * DD / 4 + 255) / 256;          // 3125
    k_init<<<copy_blocks, 256>>>((const float4*)h);

    const int scat_blocks = (NE * 16 + 255) / 256;              // 50000
    k_scatter<<<scat_blocks, 256>>>((const float4*)h, src, dst);

    const int mlp_blocks = (NN + 127) / 128;                    // 391
    k_mlp<<<mlp_blocks, 256>>>(W1, b1, W2, b2);

    k_bn<<<copy_blocks, 256>>>((const float4*)h, gamma, beta, (float4*)d_out);
}